// round 11
// baseline (speedup 1.0000x reference)
#include <cuda_runtime.h>
#include <cuda_fp16.h>
#include <cstdint>
#include <math.h>
#include <mma.h>

using namespace nvcuda;

#define B_  256
#define T_  128
#define X_  256
#define H_  1024

#define TBM 32
#define BN  64
#define BK  64
#define STAGES 4
#define ALD 72
#define BLD 72
#define A_ST (TBM * ALD)
#define B_ST (BK * BLD)
#define STAGE_HALVES (A_ST + B_ST)             // 6912
#define DYN_SMEM (STAGES * STAGE_HALVES * 2)   // 55296 B

#define NBLK 128

// ---------------- device scratch ----------------
__device__ float  g_y   [B_ * X_];
__device__ __half g_yh  [B_ * X_];
__device__ float  g_h0f [B_ * H_];
__device__ __half g_a   [B_ * H_];
__device__ __half g_b1  [B_ * H_];
__device__ __half g_b2  [B_ * H_];
__device__ __half g_b3  [B_ * H_];
__device__ float  g_bcat[1280];

// strip counters (monotonic within one kernel_launch invocation)
__device__ unsigned g_ca[8];       // fused arrivals (20 per strip per step)
__device__ unsigned g_cb[3][8];    // b1/b2/b3 arrivals (16 per strip per step)

#define WH_IN   0
#define WH_H    (256 * 1024)
#define WH_OUTA (WH_H + 3 * 1024 * 1024)
#define WH_CAT  (WH_OUTA + 1024 * 256)
#define WH_TOT  (WH_CAT + 1024 * 1280)
__device__ __half g_wh[WH_TOT];

#define CP16(dst, src) \
    asm volatile("cp.async.cg.shared.global [%0], [%1], 16;" :: "r"(dst), "l"(src))
#define CP_COMMIT() asm volatile("cp.async.commit_group;" ::: "memory")
#define CP_WAIT2()  asm volatile("cp.async.wait_group 2;" ::: "memory")

__device__ __forceinline__ unsigned ldv(const unsigned* p) {
    return *(volatile const unsigned*)p;
}
__device__ __forceinline__ void strip_wait(const unsigned* cnt, unsigned target, int tid) {
    if (tid == 0) {
        while (ldv(cnt) < target) { __nanosleep(64); }
    }
    __syncthreads();
    __threadfence();
}
__device__ __forceinline__ void strip_arrive(unsigned* cnt, int tid) {
    __syncthreads();
    if (tid == 0) {
        __threadfence();
        atomicAdd(cnt, 1u);
    }
}

// ---------------- setup kernels ----------------
__global__ void node_init_kernel(const float* __restrict__ x, float* __restrict__ out) {
    int i = blockIdx.x * blockDim.x + threadIdx.x;
    if (blockIdx.x == 0 && threadIdx.x < 8) {
        g_ca[threadIdx.x] = 0;
        g_cb[0][threadIdx.x] = 0;
        g_cb[1][threadIdx.x] = 0;
        g_cb[2][threadIdx.x] = 0;
    }
    float v = x[i];
    g_y[i]  = v;
    g_yh[i] = __float2half_rn(v);
    int b = i / X_, c = i % X_;
    out[(size_t)b * T_ * X_ + c] = v;
}

__global__ void cvt_kernel(const float* __restrict__ src, __half* __restrict__ dst, int n) {
    int i = blockIdx.x * blockDim.x + threadIdx.x;
    if (i < n) dst[i] = __float2half_rn(src[i]);
}

__global__ void pack_wout_kernel(const float* __restrict__ W_out, __half* __restrict__ wcat) {
    int i = blockIdx.x * blockDim.x + threadIdx.x;
    int k = i >> 8, n = i & 255;
    wcat[k * 1280 + n] = __float2half_rn(W_out[k * 256 + n]);
}

__global__ void bcat_kernel(const float* __restrict__ b_out, const float* __restrict__ W_in,
                            float* __restrict__ bcat) {
    int n = blockIdx.x * blockDim.x + threadIdx.x;
    if (n >= 1280) return;
    if (n < 256) bcat[n] = b_out[n];
    else {
        int c = n - 256;
        float s = 0.f;
        for (int k = 0; k < 256; k++) s += b_out[k] * W_in[k * 1024 + c];
        bcat[n] = s;
    }
}

// ---------------- one GEMM tile (device) ----------------
// MODE 0: CoutH = tanh(val + bias)   (hidden)
// MODE 1: fused out: bn<256 -> y += dt*val, store out; else h0f += dt*val, a = tanh
// MODE 2: CoutH = val (no bias)      (combo setup)
// MODE 3: h0f = val + bias; a = tanh (initial in-layer)
template <int MODE>
__device__ __forceinline__ void tile_gemm(
    const __half* __restrict__ A, const __half* __restrict__ W,
    const float* __restrict__ bias, __half* __restrict__ CoutH,
    int K, int N, int ldc, int bm, int bn,
    float* __restrict__ gy, float* __restrict__ h0f, __half* __restrict__ aout,
    float* __restrict__ outp, const float* __restrict__ ts, int t,
    __half* smem)
{
    const int tid = threadIdx.x;
    const int w   = tid >> 5;
    const int wm  = w & 1;
    const int wn  = w >> 1;

    wmma::fragment<wmma::accumulator, 16, 16, 16, float> c0;
    wmma::fill_fragment(c0, 0.0f);

    const int NIT = K / BK;

    auto loadStage = [&](int it) {
        if (it < NIT) {
            const int k0 = it * BK;
            __half* As = smem + (it % STAGES) * STAGE_HALVES;
            uint32_t asb = (uint32_t)__cvta_generic_to_shared(As);
            uint32_t bsb = (uint32_t)__cvta_generic_to_shared(As + A_ST);
            {
                int r = tid >> 3, c8 = tid & 7;
                CP16(asb + (uint32_t)(r * ALD + c8 * 8) * 2,
                     A + (size_t)(bm + r) * K + k0 + c8 * 8);
            }
            #pragma unroll
            for (int i = 0; i < 2; i++) {
                int id = tid + i * 256;
                int r = id >> 3, c8 = id & 7;
                CP16(bsb + (uint32_t)(r * BLD + c8 * 8) * 2,
                     W + (size_t)(k0 + r) * N + bn + c8 * 8);
            }
        }
        CP_COMMIT();
    };

    loadStage(0); loadStage(1); loadStage(2);

    for (int it = 0; it < NIT; it++) {
        CP_WAIT2();
        __syncthreads();

        const __half* Ab = smem + (it % STAGES) * STAGE_HALVES;
        const __half* Bb = Ab + A_ST;

        #pragma unroll
        for (int kf = 0; kf < BK / 16; kf++) {
            wmma::fragment<wmma::matrix_a, 16, 16, 16, __half, wmma::row_major> a0;
            wmma::fragment<wmma::matrix_b, 16, 16, 16, __half, wmma::row_major> b0;
            wmma::load_matrix_sync(a0, Ab + (wm * 16) * ALD + kf * 16, ALD);
            wmma::load_matrix_sync(b0, Bb + (kf * 16) * BLD + wn * 16, BLD);
            wmma::mma_sync(c0, a0, b0, c0);
        }
        loadStage(it + 3);
    }

    __syncthreads();
    float* E = reinterpret_cast<float*>(smem);
    wmma::store_matrix_sync(E + (size_t)(wm * 16) * BLD + wn * 16, c0, BLD, wmma::mem_row_major);
    __syncthreads();

    const int r     = tid >> 3;
    const int cbase = (tid & 7) * 8;

    if (MODE == 1) {
        const float dt = ts[t + 1] - ts[t];
        if (bn < 256) {
            #pragma unroll
            for (int j = 0; j < 2; j++) {
                int col = cbase + j * 4;
                int n   = bn + col;
                int yi  = (bm + r) * X_ + n;
                float4 yv = *reinterpret_cast<float4*>(&gy[yi]);
                yv.x += dt * (E[r * BLD + col + 0] + bias[n + 0]);
                yv.y += dt * (E[r * BLD + col + 1] + bias[n + 1]);
                yv.z += dt * (E[r * BLD + col + 2] + bias[n + 2]);
                yv.w += dt * (E[r * BLD + col + 3] + bias[n + 3]);
                *reinterpret_cast<float4*>(&gy[yi]) = yv;
                *reinterpret_cast<float4*>(&outp[(size_t)(bm + r) * T_ * X_ +
                                                 (size_t)(t + 1) * X_ + n]) = yv;
            }
        } else {
            #pragma unroll
            for (int j = 0; j < 2; j++) {
                int col = cbase + j * 4;
                int n   = bn + col;
                int hi  = (bm + r) * H_ + (n - 256);
                float4 hv = *reinterpret_cast<float4*>(&h0f[hi]);
                hv.x += dt * (E[r * BLD + col + 0] + bias[n + 0]);
                hv.y += dt * (E[r * BLD + col + 1] + bias[n + 1]);
                hv.z += dt * (E[r * BLD + col + 2] + bias[n + 2]);
                hv.w += dt * (E[r * BLD + col + 3] + bias[n + 3]);
                *reinterpret_cast<float4*>(&h0f[hi]) = hv;
                __half2 p0 = __halves2half2(__float2half_rn(tanhf(hv.x)), __float2half_rn(tanhf(hv.y)));
                __half2 p1 = __halves2half2(__float2half_rn(tanhf(hv.z)), __float2half_rn(tanhf(hv.w)));
                uint2 pk = make_uint2(*reinterpret_cast<uint32_t*>(&p0),
                                      *reinterpret_cast<uint32_t*>(&p1));
                *reinterpret_cast<uint2*>(&aout[hi]) = pk;
            }
        }
    } else {
        #pragma unroll
        for (int j = 0; j < 2; j++) {
            int col = cbase + j * 4;
            float4 v = *reinterpret_cast<float4*>(&E[r * BLD + col]);
            if (MODE == 0 || MODE == 3) {
                v.x += bias[bn + col + 0];
                v.y += bias[bn + col + 1];
                v.z += bias[bn + col + 2];
                v.w += bias[bn + col + 3];
            }
            if (MODE == 0) {
                __half2 p0 = __halves2half2(__float2half_rn(tanhf(v.x)), __float2half_rn(tanhf(v.y)));
                __half2 p1 = __halves2half2(__float2half_rn(tanhf(v.z)), __float2half_rn(tanhf(v.w)));
                uint2 pk = make_uint2(*reinterpret_cast<uint32_t*>(&p0),
                                      *reinterpret_cast<uint32_t*>(&p1));
                *reinterpret_cast<uint2*>(&CoutH[(size_t)(bm + r) * ldc + bn + col]) = pk;
            } else if (MODE == 2) {
                __half2 p0 = __halves2half2(__float2half_rn(v.x), __float2half_rn(v.y));
                __half2 p1 = __halves2half2(__float2half_rn(v.z), __float2half_rn(v.w));
                uint2 pk = make_uint2(*reinterpret_cast<uint32_t*>(&p0),
                                      *reinterpret_cast<uint32_t*>(&p1));
                *reinterpret_cast<uint2*>(&CoutH[(size_t)(bm + r) * ldc + bn + col]) = pk;
            } else {
                int hi = (bm + r) * ldc + bn + col;
                *reinterpret_cast<float4*>(&h0f[hi]) = v;
                __half2 p0 = __halves2half2(__float2half_rn(tanhf(v.x)), __float2half_rn(tanhf(v.y)));
                __half2 p1 = __halves2half2(__float2half_rn(tanhf(v.z)), __float2half_rn(tanhf(v.w)));
                uint2 pk = make_uint2(*reinterpret_cast<uint32_t*>(&p0),
                                      *reinterpret_cast<uint32_t*>(&p1));
                *reinterpret_cast<uint2*>(&aout[hi]) = pk;
            }
        }
    }
}

// ---------------- standalone wrapper (setup GEMMs) ----------------
template <int MODE>
__global__ void __launch_bounds__(256, 1) gemm_k(
    const __half* __restrict__ A, const __half* __restrict__ W,
    const float* __restrict__ bias, __half* __restrict__ CoutH,
    int K, int N, int ldc,
    float* __restrict__ gy, float* __restrict__ h0f, __half* __restrict__ aout,
    float* __restrict__ outp, const float* __restrict__ ts, int t)
{
    extern __shared__ __half smem[];
    tile_gemm<MODE>(A, W, bias, CoutH, K, N, ldc,
                    blockIdx.y * TBM, blockIdx.x * BN,
                    gy, h0f, aout, outp, ts, t, smem);
}

// ---------------- persistent dataflow kernel ----------------
__global__ void __launch_bounds__(256, 1) node_persist(
    const __half* __restrict__ wh, const float* __restrict__ b_h,
    const float* __restrict__ bcat,
    float* __restrict__ gy, float* __restrict__ h0f,
    __half* __restrict__ a, __half* __restrict__ b1,
    __half* __restrict__ b2, __half* __restrict__ b3,
    float* __restrict__ outp, const float* __restrict__ ts)
{
    extern __shared__ __half smem[];
    const int c   = blockIdx.x;          // 0..127
    const int tid = threadIdx.x;
    const int mH  = c >> 4;              // strip 0..7
    const int nH  = c & 15;              // n-tile 0..15
    const int f1  = c;                   // fused tile 1
    const int f2  = (c < 32) ? (128 + c) : -1;

    const __half* Wh0 = wh + WH_H + 0 * 1024 * 1024;
    const __half* Wh1 = wh + WH_H + 1 * 1024 * 1024;
    const __half* Wh2 = wh + WH_H + 2 * 1024 * 1024;
    const __half* Wc  = wh + WH_CAT;

    for (int t = 0; t < T_ - 1; t++) {
        const unsigned base = 16u * (unsigned)(t + 1);

        // L0: b1 = tanh-producer input a @ Wh0
        strip_wait(&g_ca[mH], 20u * (unsigned)t, tid);
        tile_gemm<0>(a, Wh0, b_h + 0 * H_, b1, 1024, 1024, 1024, mH * TBM, nH * BN,
                     nullptr, nullptr, nullptr, nullptr, nullptr, 0, smem);
        strip_arrive(&g_cb[0][mH], tid);

        // L1
        strip_wait(&g_cb[0][mH], base, tid);
        tile_gemm<0>(b1, Wh1, b_h + 1 * H_, b2, 1024, 1024, 1024, mH * TBM, nH * BN,
                     nullptr, nullptr, nullptr, nullptr, nullptr, 0, smem);
        strip_arrive(&g_cb[1][mH], tid);

        // L2
        strip_wait(&g_cb[1][mH], base, tid);
        tile_gemm<0>(b2, Wh2, b_h + 2 * H_, b3, 1024, 1024, 1024, mH * TBM, nH * BN,
                     nullptr, nullptr, nullptr, nullptr, nullptr, 0, smem);
        strip_arrive(&g_cb[2][mH], tid);

        // L3 fused (1 or 2 tiles)
        {
            const int fm = f1 / 20, fn = f1 % 20;
            strip_wait(&g_cb[2][fm], base, tid);
            tile_gemm<1>(b3, Wc, bcat, nullptr, 1024, 1280, 0, fm * TBM, fn * BN,
                         gy, h0f, a, outp, ts, t, smem);
            strip_arrive(&g_ca[fm], tid);
        }
        if (f2 >= 0) {
            const int fm = f2 / 20, fn = f2 % 20;
            strip_wait(&g_cb[2][fm], base, tid);
            tile_gemm<1>(b3, Wc, bcat, nullptr, 1024, 1280, 0, fm * TBM, fn * BN,
                         gy, h0f, a, outp, ts, t, smem);
            strip_arrive(&g_ca[fm], tid);
        }
    }
}

// ---------------- host ----------------
extern "C" void kernel_launch(void* const* d_in, const int* in_sizes, int n_in,
                              void* d_out, int out_size)
{
    const float* x     = (const float*)d_in[0];
    const float* ts    = (const float*)d_in[1];
    const float* W_in  = (const float*)d_in[2];
    const float* b_in  = (const float*)d_in[3];
    const float* W_h   = (const float*)d_in[4];
    const float* b_h   = (const float*)d_in[5];
    const float* W_out = (const float*)d_in[6];
    const float* b_out = (const float*)d_in[7];
    float* out = (float*)d_out;

    float  *py, *ph0f, *pbcat;
    __half *pyh, *pa, *pb1, *pb2, *pb3, *pwh;
    cudaGetSymbolAddress((void**)&py,   g_y);
    cudaGetSymbolAddress((void**)&pyh,  g_yh);
    cudaGetSymbolAddress((void**)&ph0f, g_h0f);
    cudaGetSymbolAddress((void**)&pa,   g_a);
    cudaGetSymbolAddress((void**)&pb1,  g_b1);
    cudaGetSymbolAddress((void**)&pb2,  g_b2);
    cudaGetSymbolAddress((void**)&pb3,  g_b3);
    cudaGetSymbolAddress((void**)&pbcat, g_bcat);
    cudaGetSymbolAddress((void**)&pwh,  g_wh);

    cudaFuncSetAttribute(gemm_k<2>, cudaFuncAttributeMaxDynamicSharedMemorySize, DYN_SMEM);
    cudaFuncSetAttribute(gemm_k<3>, cudaFuncAttributeMaxDynamicSharedMemorySize, DYN_SMEM);
    cudaFuncSetAttribute(node_persist, cudaFuncAttributeMaxDynamicSharedMemorySize, DYN_SMEM);

    // ---- one-time setup ----
    cvt_kernel<<<(256 * 1024 + 255) / 256, 256>>>(W_in,  pwh + WH_IN,   256 * 1024);
    cvt_kernel<<<(3 * 1024 * 1024 + 255) / 256, 256>>>(W_h, pwh + WH_H, 3 * 1024 * 1024);
    cvt_kernel<<<(1024 * 256 + 255) / 256, 256>>>(W_out, pwh + WH_OUTA, 1024 * 256);
    pack_wout_kernel<<<1024, 256>>>(W_out, pwh + WH_CAT);
    bcat_kernel<<<5, 256>>>(b_out, W_in, pbcat);

    // W_combo = W_out @ W_in -> W_cat columns [256, 1280)
    gemm_k<2><<<dim3(16, 32), 256, DYN_SMEM>>>(
        pwh + WH_OUTA, pwh + WH_IN, (const float*)nullptr, pwh + WH_CAT + 256,
        256, 1024, 1280,
        (float*)nullptr, (float*)nullptr, (__half*)nullptr, (float*)nullptr,
        (const float*)nullptr, 0);

    node_init_kernel<<<(B_ * X_) / 256, 256>>>(x, out);

    // h0f = x @ W_in + b_in ; a = tanh(h0f)
    gemm_k<3><<<dim3(16, 8), 256, DYN_SMEM>>>(
        pyh, pwh + WH_IN, b_in, (__half*)nullptr,
        256, 1024, 1024,
        (float*)nullptr, ph0f, pa, (float*)nullptr, (const float*)nullptr, 0);

    // ---- persistent dataflow loop ----
    node_persist<<<NBLK, 256, DYN_SMEM>>>(
        pwh, b_h, pbcat, py, ph0f, pa, pb1, pb2, pb3, out, ts);
}

// round 12
// speedup vs baseline: 1.1452x; 1.1452x over previous
#include <cuda_runtime.h>
#include <cuda_fp16.h>
#include <cstdint>
#include <math.h>
#include <mma.h>

using namespace nvcuda;

#define B_  256
#define T_  128
#define X_  256
#define H_  1024

#define BN  64
#define BK  128
#define STAGES 4
#define ALD (BK + 8)                  // 136
#define BLD (BN + 8)                  // 72
#define B_ST (BK * BLD)               // 9216 halves
#define A_ST(TBM)        ((TBM) * ALD)
#define STG_H(TBM)       (A_ST(TBM) + B_ST)
#define DYN_SMEM(TBM)    (STAGES * STG_H(TBM) * 2)   // 108544 (32) / 143360 (64)

// ---------------- device scratch ----------------
__device__ float  g_y   [B_ * X_];
__device__ __half g_yh  [B_ * X_];
__device__ float  g_h0f [B_ * H_];
__device__ __half g_a   [B_ * H_];
__device__ __half g_b1  [B_ * H_];
__device__ __half g_b2  [B_ * H_];
__device__ __half g_b3  [B_ * H_];
__device__ float  g_bcat[1280];

#define WH_IN   0
#define WH_H    (256 * 1024)
#define WH_OUTA (WH_H + 3 * 1024 * 1024)
#define WH_CAT  (WH_OUTA + 1024 * 256)
#define WH_TOT  (WH_CAT + 1024 * 1280)
__device__ __half g_wh[WH_TOT];

#define CP16(dst, src) \
    asm volatile("cp.async.cg.shared.global [%0], [%1], 16;" :: "r"(dst), "l"(src))
#define CP_COMMIT() asm volatile("cp.async.commit_group;" ::: "memory")
#define CP_WAIT2()  asm volatile("cp.async.wait_group 2;" ::: "memory")

// ---------------- setup kernels ----------------
__global__ void node_init_kernel(const float* __restrict__ x, float* __restrict__ out) {
    int i = blockIdx.x * blockDim.x + threadIdx.x;
    float v = x[i];
    g_y[i]  = v;
    g_yh[i] = __float2half_rn(v);
    int b = i / X_, c = i % X_;
    out[(size_t)b * T_ * X_ + c] = v;
}

__global__ void cvt_kernel(const float* __restrict__ src, __half* __restrict__ dst, int n) {
    int i = blockIdx.x * blockDim.x + threadIdx.x;
    if (i < n) dst[i] = __float2half_rn(src[i]);
}

__global__ void pack_wout_kernel(const float* __restrict__ W_out, __half* __restrict__ wcat) {
    int i = blockIdx.x * blockDim.x + threadIdx.x;    // 1024*256
    int k = i >> 8, n = i & 255;
    wcat[k * 1280 + n] = __float2half_rn(W_out[k * 256 + n]);
}

__global__ void bcat_kernel(const float* __restrict__ b_out, const float* __restrict__ W_in,
                            float* __restrict__ bcat) {
    int n = blockIdx.x * blockDim.x + threadIdx.x;
    if (n >= 1280) return;
    if (n < 256) bcat[n] = b_out[n];
    else {
        int c = n - 256;
        float s = 0.f;
        for (int k = 0; k < 256; k++) s += b_out[k] * W_in[k * 1024 + c];
        bcat[n] = s;
    }
}

// ---------------- WMMA fp16 GEMM, BK=128, templated tile height ----------------
// MODE 0: CoutH = tanh(val + bias)   (hidden)
// MODE 1: fused out: bn<256 -> y += dt*val, store out; else h0f += dt*val, a = tanh
// MODE 2: CoutH = val (no bias)      (combo setup)
// MODE 3: h0f = val + bias; a = tanh (initial in-layer)
template <int TBM, int MODE>
__global__ void __launch_bounds__(256, 1) gemm_k(
    const __half* __restrict__ A, const __half* __restrict__ W,
    const float* __restrict__ bias, __half* __restrict__ CoutH,
    int K, int N, int ldc,
    float* __restrict__ gy, float* __restrict__ h0f, __half* __restrict__ aout,
    float* __restrict__ outp, const float* __restrict__ ts, int t)
{
    extern __shared__ __half smem[];
    constexpr int AST = A_ST(TBM);
    constexpr int SH  = STG_H(TBM);

    const int tid = threadIdx.x;
    const int bm  = blockIdx.y * TBM;
    const int bn  = blockIdx.x * BN;
    const int w   = tid >> 5;
    const int wm  = (TBM == 32) ? (w & 1) : (w & 3);
    const int wn  = (TBM == 32) ? (w >> 1) : (w >> 2);

    wmma::fragment<wmma::accumulator, 16, 16, 16, float> c0, c1;
    wmma::fill_fragment(c0, 0.0f);
    if (TBM == 64) wmma::fill_fragment(c1, 0.0f);

    const int NIT = K / BK;

    auto loadStage = [&](int it) {
        if (it < NIT) {
            const int k0 = it * BK;
            __half* As = smem + (it % STAGES) * SH;
            uint32_t asb = (uint32_t)__cvta_generic_to_shared(As);
            uint32_t bsb = (uint32_t)__cvta_generic_to_shared(As + AST);
            constexpr int ACH = TBM * BK / 8 / 256;   // chunks per thread (2 or 4)
            #pragma unroll
            for (int i = 0; i < ACH; i++) {
                int id = tid + i * 256;
                int r = id >> 4, c8 = id & 15;        // 16 chunks of 8 per row
                CP16(asb + (uint32_t)(r * ALD + c8 * 8) * 2,
                     A + (size_t)(bm + r) * K + k0 + c8 * 8);
            }
            #pragma unroll
            for (int i = 0; i < 4; i++) {             // B: 128 rows x 8 chunks
                int id = tid + i * 256;
                int r = id >> 3, c8 = id & 7;
                CP16(bsb + (uint32_t)(r * BLD + c8 * 8) * 2,
                     W + (size_t)(k0 + r) * N + bn + c8 * 8);
            }
        }
        CP_COMMIT();
    };

    loadStage(0); loadStage(1); loadStage(2);

    for (int it = 0; it < NIT; it++) {
        CP_WAIT2();
        __syncthreads();

        const __half* Ab = smem + (it % STAGES) * SH;
        const __half* Bb = Ab + AST;

        #pragma unroll
        for (int kf = 0; kf < BK / 16; kf++) {
            wmma::fragment<wmma::matrix_a, 16, 16, 16, __half, wmma::row_major> a0;
            wmma::load_matrix_sync(a0, Ab + (wm * 16) * ALD + kf * 16, ALD);
            if (TBM == 32) {
                wmma::fragment<wmma::matrix_b, 16, 16, 16, __half, wmma::row_major> b0;
                wmma::load_matrix_sync(b0, Bb + (kf * 16) * BLD + wn * 16, BLD);
                wmma::mma_sync(c0, a0, b0, c0);
            } else {
                wmma::fragment<wmma::matrix_b, 16, 16, 16, __half, wmma::row_major> b0, b1;
                wmma::load_matrix_sync(b0, Bb + (kf * 16) * BLD + wn * 32 +  0, BLD);
                wmma::load_matrix_sync(b1, Bb + (kf * 16) * BLD + wn * 32 + 16, BLD);
                wmma::mma_sync(c0, a0, b0, c0);
                wmma::mma_sync(c1, a0, b1, c1);
            }
        }
        loadStage(it + 3);
    }

    // ---- epilogue ----
    __syncthreads();
    float* E = reinterpret_cast<float*>(smem);   // [TBM][BLD] fp32
    if (TBM == 32) {
        wmma::store_matrix_sync(E + (size_t)(wm * 16) * BLD + wn * 16, c0, BLD, wmma::mem_row_major);
    } else {
        wmma::store_matrix_sync(E + (size_t)(wm * 16) * BLD + wn * 32 +  0, c0, BLD, wmma::mem_row_major);
        wmma::store_matrix_sync(E + (size_t)(wm * 16) * BLD + wn * 32 + 16, c1, BLD, wmma::mem_row_major);
    }
    __syncthreads();

    constexpr int NCH = (TBM == 32) ? 2 : 4;
    const int r     = (TBM == 32) ? (tid >> 3) : (tid >> 2);
    const int cbase = (TBM == 32) ? ((tid & 7) * 8) : ((tid & 3) * 16);

    if (MODE == 1) {
        const float dt = ts[t + 1] - ts[t];
        if (bn < 256) {
            #pragma unroll
            for (int j = 0; j < NCH; j++) {
                int col = cbase + j * 4;
                int n   = bn + col;
                int yi  = (bm + r) * X_ + n;
                float4 yv = *reinterpret_cast<float4*>(&gy[yi]);
                yv.x += dt * (E[r * BLD + col + 0] + bias[n + 0]);
                yv.y += dt * (E[r * BLD + col + 1] + bias[n + 1]);
                yv.z += dt * (E[r * BLD + col + 2] + bias[n + 2]);
                yv.w += dt * (E[r * BLD + col + 3] + bias[n + 3]);
                *reinterpret_cast<float4*>(&gy[yi]) = yv;
                *reinterpret_cast<float4*>(&outp[(size_t)(bm + r) * T_ * X_ +
                                                 (size_t)(t + 1) * X_ + n]) = yv;
            }
        } else {
            #pragma unroll
            for (int j = 0; j < NCH; j++) {
                int col = cbase + j * 4;
                int n   = bn + col;
                int hi  = (bm + r) * H_ + (n - 256);
                float4 hv = *reinterpret_cast<float4*>(&h0f[hi]);
                hv.x += dt * (E[r * BLD + col + 0] + bias[n + 0]);
                hv.y += dt * (E[r * BLD + col + 1] + bias[n + 1]);
                hv.z += dt * (E[r * BLD + col + 2] + bias[n + 2]);
                hv.w += dt * (E[r * BLD + col + 3] + bias[n + 3]);
                *reinterpret_cast<float4*>(&h0f[hi]) = hv;
                __half2 p0 = __halves2half2(__float2half_rn(tanhf(hv.x)), __float2half_rn(tanhf(hv.y)));
                __half2 p1 = __halves2half2(__float2half_rn(tanhf(hv.z)), __float2half_rn(tanhf(hv.w)));
                uint2 pk = make_uint2(*reinterpret_cast<uint32_t*>(&p0),
                                      *reinterpret_cast<uint32_t*>(&p1));
                *reinterpret_cast<uint2*>(&aout[hi]) = pk;
            }
        }
    } else {
        #pragma unroll
        for (int j = 0; j < NCH; j++) {
            int col = cbase + j * 4;
            float4 v = *reinterpret_cast<float4*>(&E[r * BLD + col]);
            if (MODE == 0 || MODE == 3) {
                v.x += bias[bn + col + 0];
                v.y += bias[bn + col + 1];
                v.z += bias[bn + col + 2];
                v.w += bias[bn + col + 3];
            }
            if (MODE == 0) {
                __half2 p0 = __halves2half2(__float2half_rn(tanhf(v.x)), __float2half_rn(tanhf(v.y)));
                __half2 p1 = __halves2half2(__float2half_rn(tanhf(v.z)), __float2half_rn(tanhf(v.w)));
                uint2 pk = make_uint2(*reinterpret_cast<uint32_t*>(&p0),
                                      *reinterpret_cast<uint32_t*>(&p1));
                *reinterpret_cast<uint2*>(&CoutH[(size_t)(bm + r) * ldc + bn + col]) = pk;
            } else if (MODE == 2) {
                __half2 p0 = __halves2half2(__float2half_rn(v.x), __float2half_rn(v.y));
                __half2 p1 = __halves2half2(__float2half_rn(v.z), __float2half_rn(v.w));
                uint2 pk = make_uint2(*reinterpret_cast<uint32_t*>(&p0),
                                      *reinterpret_cast<uint32_t*>(&p1));
                *reinterpret_cast<uint2*>(&CoutH[(size_t)(bm + r) * ldc + bn + col]) = pk;
            } else {  // MODE 3
                int hi = (bm + r) * ldc + bn + col;
                *reinterpret_cast<float4*>(&h0f[hi]) = v;
                __half2 p0 = __halves2half2(__float2half_rn(tanhf(v.x)), __float2half_rn(tanhf(v.y)));
                __half2 p1 = __halves2half2(__float2half_rn(tanhf(v.z)), __float2half_rn(tanhf(v.w)));
                uint2 pk = make_uint2(*reinterpret_cast<uint32_t*>(&p0),
                                      *reinterpret_cast<uint32_t*>(&p1));
                *reinterpret_cast<uint2*>(&aout[hi]) = pk;
            }
        }
    }
}

// ---------------- host ----------------
extern "C" void kernel_launch(void* const* d_in, const int* in_sizes, int n_in,
                              void* d_out, int out_size)
{
    const float* x     = (const float*)d_in[0];
    const float* ts    = (const float*)d_in[1];
    const float* W_in  = (const float*)d_in[2];
    const float* b_in  = (const float*)d_in[3];
    const float* W_h   = (const float*)d_in[4];
    const float* b_h   = (const float*)d_in[5];
    const float* W_out = (const float*)d_in[6];
    const float* b_out = (const float*)d_in[7];
    float* out = (float*)d_out;

    float  *py, *ph0f, *pbcat;
    __half *pyh, *pa, *pb1, *pb2, *pb3, *pwh;
    cudaGetSymbolAddress((void**)&py,   g_y);
    cudaGetSymbolAddress((void**)&pyh,  g_yh);
    cudaGetSymbolAddress((void**)&ph0f, g_h0f);
    cudaGetSymbolAddress((void**)&pa,   g_a);
    cudaGetSymbolAddress((void**)&pb1,  g_b1);
    cudaGetSymbolAddress((void**)&pb2,  g_b2);
    cudaGetSymbolAddress((void**)&pb3,  g_b3);
    cudaGetSymbolAddress((void**)&pbcat, g_bcat);
    cudaGetSymbolAddress((void**)&pwh,  g_wh);

    cudaFuncSetAttribute(gemm_k<32, 0>, cudaFuncAttributeMaxDynamicSharedMemorySize, DYN_SMEM(32));
    cudaFuncSetAttribute(gemm_k<64, 1>, cudaFuncAttributeMaxDynamicSharedMemorySize, DYN_SMEM(64));
    cudaFuncSetAttribute(gemm_k<32, 2>, cudaFuncAttributeMaxDynamicSharedMemorySize, DYN_SMEM(32));
    cudaFuncSetAttribute(gemm_k<32, 3>, cudaFuncAttributeMaxDynamicSharedMemorySize, DYN_SMEM(32));

    // ---- one-time setup ----
    cvt_kernel<<<(256 * 1024 + 255) / 256, 256>>>(W_in,  pwh + WH_IN,   256 * 1024);
    cvt_kernel<<<(3 * 1024 * 1024 + 255) / 256, 256>>>(W_h, pwh + WH_H, 3 * 1024 * 1024);
    cvt_kernel<<<(1024 * 256 + 255) / 256, 256>>>(W_out, pwh + WH_OUTA, 1024 * 256);
    pack_wout_kernel<<<1024, 256>>>(W_out, pwh + WH_CAT);
    bcat_kernel<<<5, 256>>>(b_out, W_in, pbcat);

    // W_combo = W_out @ W_in -> W_cat columns [256, 1280)
    gemm_k<32, 2><<<dim3(16, 32), 256, DYN_SMEM(32)>>>(
        pwh + WH_OUTA, pwh + WH_IN, (const float*)nullptr, pwh + WH_CAT + 256,
        256, 1024, 1280,
        (float*)nullptr, (float*)nullptr, (__half*)nullptr, (float*)nullptr,
        (const float*)nullptr, 0);

    node_init_kernel<<<(B_ * X_) / 256, 256>>>(x, out);

    // h0f = x @ W_in + b_in ; a = tanh(h0f)
    gemm_k<32, 3><<<dim3(16, 8), 256, DYN_SMEM(32)>>>(
        pyh, pwh + WH_IN, b_in, (__half*)nullptr,
        256, 1024, 1024,
        (float*)nullptr, ph0f, pa, (float*)nullptr, (const float*)nullptr, 0);

    // ---- time loop: 4 plain-launched GEMMs per step ----
    dim3 blk(256);
    dim3 gridH(16, 8);    // hidden: 128 CTAs (TBM=32)
    dim3 gridF(20, 4);    // fused:  80 CTAs (TBM=64), single wave

    const __half* Wh = pwh + WH_H;

    for (int t = 0; t < T_ - 1; t++) {
        gemm_k<32, 0><<<gridH, blk, DYN_SMEM(32)>>>(
            pa,  Wh + 0 * 1024 * 1024, b_h + 0 * H_, pb1, 1024, 1024, 1024,
            (float*)nullptr, (float*)nullptr, (__half*)nullptr, (float*)nullptr,
            (const float*)nullptr, 0);
        gemm_k<32, 0><<<gridH, blk, DYN_SMEM(32)>>>(
            pb1, Wh + 1 * 1024 * 1024, b_h + 1 * H_, pb2, 1024, 1024, 1024,
            (float*)nullptr, (float*)nullptr, (__half*)nullptr, (float*)nullptr,
            (const float*)nullptr, 0);
        gemm_k<32, 0><<<gridH, blk, DYN_SMEM(32)>>>(
            pb2, Wh + 2 * 1024 * 1024, b_h + 2 * H_, pb3, 1024, 1024, 1024,
            (float*)nullptr, (float*)nullptr, (__half*)nullptr, (float*)nullptr,
            (const float*)nullptr, 0);
        gemm_k<64, 1><<<gridF, blk, DYN_SMEM(64)>>>(
            pb3, pwh + WH_CAT, pbcat, (__half*)nullptr, 1024, 1280, 0,
            py, ph0f, pa, out, ts, t);
    }
}